// round 9
// baseline (speedup 1.0000x reference)
#include <cuda_runtime.h>
#include <math.h>

#define BB 16
#define TT 200
#define UU 100
#define U1 101
#define V1 129
#define ST 104                    // padded row stride (mult of 8 -> float4 aligned)
#define LOG2E 1.4426950408889634f
#define LN2   0.6931471805599453f
#define NINF  (-INFINITY)

// Scratch: LINEAR softmax probs, padded stride. Label table shifted +1 col.
// Zero-init device globals: unwritten rows/cols are load-bearing guards
// (rows >= logit_len stay 0 and are COPIED IN FULL to SMEM — the label
// table's negative-row guard reads land in the blank table's tail rows).
__device__ __align__(16) float g_blank[BB * TT * ST];
__device__ __align__(16) float g_label[BB * TT * ST];
__device__ float    g_loss[BB];
__device__ unsigned g_cnt;

__device__ __forceinline__ float ex2f_raw(float x) {
    float y; asm("ex2.approx.f32 %0, %1;" : "=f"(y) : "f"(x)); return y;
}
__device__ __forceinline__ float lg2f_raw(float x) {
    float y; asm("lg2.approx.f32 %0, %1;" : "=f"(y) : "f"(x)); return y;
}
__device__ __forceinline__ float rcpf_raw(float x) {
    float y; asm("rcp.approx.f32 %0, %1;" : "=f"(y) : "f"(x)); return y;
}

// ---------------------------------------------------------------------------
// Kernel 1: softmax. grid=(4,T,B), no divisions. Warp handles 4 u-rows.
// Stores LINEAR probs: blank[t][u], label shifted to [t][u+1].
// ---------------------------------------------------------------------------
__global__ void __launch_bounds__(256) lsm_kernel(
    const float* __restrict__ logits,
    const int*   __restrict__ labels,
    const int*   __restrict__ logit_lens,
    const int*   __restrict__ y_lens)
{
    const unsigned FULL = 0xffffffffu;
    int b = blockIdx.z;
    int t = blockIdx.y;
    int tl = __ldg(&logit_lens[b]);
    if (t >= tl) return;
    int yl = __ldg(&y_lens[b]);

    int warp = threadIdx.x >> 5;
    int lane = threadIdx.x & 31;
    int u_base = (blockIdx.x * 8 + warp) * 4;
    if (u_base > yl || u_base >= U1) return;

    int rowbase = (b * TT + t) * U1;

    bool val[4];
    #pragma unroll
    for (int r = 0; r < 4; r++) {
        int u = u_base + r;
        val[r] = (u <= yl) && (u < U1);
    }

    float e[4][5];
    #pragma unroll
    for (int r = 0; r < 4; r++) {
        if (val[r]) {
            const float* rp = logits + (size_t)(rowbase + u_base + r) * V1;
            e[r][0] = ex2f_raw(rp[lane]       * LOG2E);
            e[r][1] = ex2f_raw(rp[lane + 32]  * LOG2E);
            e[r][2] = ex2f_raw(rp[lane + 64]  * LOG2E);
            e[r][3] = ex2f_raw(rp[lane + 96]  * LOG2E);
            e[r][4] = (lane == 0) ? ex2f_raw(rp[128] * LOG2E) : 0.0f;
        }
    }

    float s[4];
    #pragma unroll
    for (int r = 0; r < 4; r++)
        s[r] = val[r] ? e[r][0] + e[r][1] + e[r][2] + e[r][3] + e[r][4] : 0.0f;
    #pragma unroll
    for (int o = 16; o > 0; o >>= 1) {
        #pragma unroll
        for (int r = 0; r < 4; r++)
            s[r] += __shfl_xor_sync(FULL, s[r], o);
    }

    int outbase = (b * TT + t) * ST;
    #pragma unroll
    for (int r = 0; r < 4; r++) {
        if (!val[r]) continue;
        int u = u_base + r;
        float rinv = rcpf_raw(s[r]);
        if (u < UU) {
            int lab  = __ldg(&labels[b * UU + u]);
            int slot = lab >> 5;
            int src  = lab & 31;
            float vsel = (slot == 0) ? e[r][0] :
                         (slot == 1) ? e[r][1] :
                         (slot == 2) ? e[r][2] :
                         (slot == 3) ? e[r][3] : e[r][4];
            float lv = __shfl_sync(FULL, vsel, src);
            if (lane == 0)
                g_label[outbase + u + 1] = lv * rinv;
        }
        if (lane == 0)
            g_blank[outbase + u] = e[r][0] * rinv;
    }
}

// ---------------------------------------------------------------------------
// Kernel 2: linear-domain wavefront DP, 8-row x 4-col parallelogram blocks.
// Branch-free, integer scale frames, tail shfls, TAIL loads directly into
// the live coefficient registers (no double-buffer copy).
// ---------------------------------------------------------------------------
__global__ void __launch_bounds__(128) dp_kernel(
    const int* __restrict__ logit_lens,
    const int* __restrict__ y_lens,
    float* __restrict__ out)
{
    extern __shared__ float sm[];
    float* sB = sm + 1024;                // 1024-float zeroed front guard
    float* sL = sB + TT * ST;

    int b   = blockIdx.x;
    int tid = threadIdx.x;
    int tl  = logit_lens[b];

    for (int i = tid; i < 1024; i += 128) sm[i] = 0.0f;
    __syncthreads();
    if (tid < 8) sB[-ST * (tid + 1)] = 1.0f;   // seed col0 in guard rows -1..-8
    {
        const float4* srcB = (const float4*)(g_blank + b * TT * ST);
        const float4* srcL = (const float4*)(g_label + b * TT * ST);
        float4* dB = (float4*)sB;
        float4* dL = (float4*)sL;
        #pragma unroll 4
        for (int i = tid; i < (TT * ST) / 4; i += 128) {   // FULL table: tail zeros are guards
            dB[i] = srcB[i];
            dL[i] = srcL[i];
        }
    }
    __syncthreads();
    if (tid >= 32) return;

    const unsigned FULL = 0xffffffffu;
    int lane  = tid;
    int u0    = lane * 4;
    int yl    = y_lens[b];
    int tlast = tl - 1;
    int pad   = 7 - (tlast & 7);          // tlast lands on block row 7
    int t8max = (tlast >> 3) * 8;
    int laneyl = yl >> 2, cyl = yl & 3;
    int sfin  = laneyl + (tlast >> 3);
    int S     = sfin + 1;
    float fzero = (lane == 0) ? 0.0f : 1.0f;

    float c0 = (lane == 0) ? 1.0f : 0.0f;
    float c1 = 0.f, c2 = 0.f, c3 = 0.f;
    float b3[8], bnd[8];
    #pragma unroll
    for (int k = 0; k < 8; k++) { b3[k] = 0.f; bnd[k] = 0.f; }
    int   Mi = 0, Ml = 0;
    bool  dead = (lane != 0);             // cmax==0 flag, carried across steps
    float finL = 1.f; int finM = 0;

    // initial coefficient load (s=0): t0 clamped to 0 for all lanes
    float4 Bc[8], Lc[8];
    {
        int ib = (-pad - 1) * ST + u0;
        int il = (-pad) * ST + u0;
        #pragma unroll
        for (int k = 0; k < 8; k++) {
            Bc[k] = *(const float4*)(sB + ib + k * ST);
            Lc[k] = *(const float4*)(sL + il + k * ST);
        }
    }

    for (int s = 0; s < S; s++) {
        // --- scale reconcile (pure ALU, branch-free) ---
        int  Mn   = dead ? Ml : Mi;
        int  dM   = Ml - Mn;
        dM = dM < -127 ? -127 : (dM > 127 ? 127 : dM);
        float f = __int_as_float((127 + dM) << 23) * fzero;
        Mi = Mn;
        #pragma unroll
        for (int k = 0; k < 8; k++) bnd[k] *= f;

        // --- 8x4 FMA chain ---
        float v0 = c0, v1 = c1, v2 = c2, v3 = c3;
        #pragma unroll
        for (int r = 0; r < 8; r++) {
            float w0 = fmaf(v0, Bc[r].x, bnd[r] * Lc[r].x);
            float w1 = fmaf(v1, Bc[r].y, w0 * Lc[r].y);
            float w2 = fmaf(v2, Bc[r].z, w1 * Lc[r].z);
            float w3 = fmaf(v3, Bc[r].w, w2 * Lc[r].w);
            v0 = w0; v1 = w1; v2 = w2; v3 = w3;
            b3[r] = w3;
        }

        // --- capture final cell (frame Mi, pre-rescale) ---
        bool hit = (s == sfin) & (lane == laneyl);
        float selc = (cyl == 0) ? v0 : (cyl == 1) ? v1 : (cyl == 2) ? v2 : v3;
        finL = hit ? selc : finL;
        finM = hit ? Mi   : finM;

        // --- branch-free power-of-2 rescale ---
        float cmax = fmaxf(fmaxf(v0, v1), fmaxf(v2, v3));
        int ebits = __float_as_int(cmax) >> 23;
        dead = (ebits == 0);
        int  se = dead ? 127 : (254 - ebits);
        float sc = __int_as_float(se << 23);
        Mi += dead ? 0 : (ebits - 127);
        c0 = v0 * sc; c1 = v1 * sc; c2 = v2 * sc; c3 = v3 * sc;
        #pragma unroll
        for (int k = 0; k < 8; k++) b3[k] *= sc;

        // --- tail shfls (latency overlaps loop-back) ---
        #pragma unroll
        for (int k = 0; k < 8; k++)
            bnd[k] = __shfl_up_sync(FULL, b3[k], 1);
        Ml = __shfl_up_sync(FULL, Mi, 1);

        // --- tail loads for step s+1, directly into live registers ---
        {
            int t0n = 8 * (s + 1 - lane);
            t0n = t0n < 0 ? 0 : (t0n > t8max ? t8max : t0n);
            int ibn = (t0n - pad - 1) * ST + u0;
            int iln = (t0n - pad) * ST + u0;
            #pragma unroll
            for (int k = 0; k < 8; k++) {
                Bc[k] = *(const float4*)(sB + ibn + k * ST);
                Lc[k] = *(const float4*)(sL + iln + k * ST);
            }
        }
    }

    float fL = __shfl_sync(FULL, finL, laneyl);
    int   fM = __shfl_sync(FULL, finM, laneyl);
    if (lane == 0) {
        float total2 = lg2f_raw(fL) + (float)fM + lg2f_raw(sB[tlast * ST + yl]);
        float loss = -total2 * LN2 / (float)yl;
        g_loss[b] = loss;
        __threadfence();
        unsigned ticket = atomicAdd(&g_cnt, 1);
        if (ticket == BB - 1) {
            __threadfence();
            float ssum = 0.0f;
            #pragma unroll
            for (int i = 0; i < BB; i++) ssum += g_loss[i];
            out[0] = ssum / (float)BB;
            g_cnt = 0;
        }
    }
}

extern "C" void kernel_launch(void* const* d_in, const int* in_sizes, int n_in,
                              void* d_out, int out_size)
{
    const float* logits     = (const float*)d_in[0];
    const int*   labels     = (const int*)d_in[1];
    const int*   logit_lens = (const int*)d_in[2];
    const int*   y_lens     = (const int*)d_in[3];
    float* out = (float*)d_out;

    dim3 grid(4, TT, BB);
    lsm_kernel<<<grid, 256>>>(logits, labels, logit_lens, y_lens);

    size_t smem = (size_t)(1024 + 2 * TT * ST) * sizeof(float);
    cudaFuncSetAttribute(dp_kernel, cudaFuncAttributeMaxDynamicSharedMemorySize, (int)smem);
    dp_kernel<<<BB, 128, smem>>>(logit_lens, y_lens, out);
}

// round 11
// speedup vs baseline: 1.2158x; 1.2158x over previous
#include <cuda_runtime.h>
#include <cstdint>
#include <math.h>

#define BB 16
#define TT 200
#define UU 100
#define U1 101
#define V1 129
#define ST 104                    // padded row stride (mult of 8 -> float4 aligned)
#define RR 8                      // rows per warp in lsm
#define LOG2E 1.4426950408889634f
#define LN2   0.6931471805599453f
#define NINF  (-INFINITY)

// Scratch: LINEAR softmax probs, padded stride. Label table shifted +1 col.
// Zero-init device globals: unwritten rows/cols are load-bearing guards.
__device__ __align__(16) float g_blank[BB * TT * ST];
__device__ __align__(16) float g_label[BB * TT * ST];
__device__ float    g_loss[BB];
__device__ unsigned g_cnt;

__device__ __forceinline__ float ex2f_raw(float x) {
    float y; asm("ex2.approx.f32 %0, %1;" : "=f"(y) : "f"(x)); return y;
}
__device__ __forceinline__ float lg2f_raw(float x) {
    float y; asm("lg2.approx.f32 %0, %1;" : "=f"(y) : "f"(x)); return y;
}
__device__ __forceinline__ float rcpf_raw(float x) {
    float y; asm("rcp.approx.f32 %0, %1;" : "=f"(y) : "f"(x)); return y;
}
__device__ __forceinline__ void cp_async16(unsigned int saddr, const void* gaddr) {
    asm volatile("cp.async.cg.shared.global [%0], [%1], 16;"
                 :: "r"(saddr), "l"(gaddr));
}

// ---------------------------------------------------------------------------
// Kernel 1: softmax. grid=(2,T,B). Warp handles 8 u-rows, branch-free loads
// (clamped row index), early label-select shfl to shrink live registers.
// Stores LINEAR probs: blank[t][u], label shifted to [t][u+1].
// ---------------------------------------------------------------------------
__global__ void __launch_bounds__(256) lsm_kernel(
    const float* __restrict__ logits,
    const int*   __restrict__ labels,
    const int*   __restrict__ logit_lens,
    const int*   __restrict__ y_lens)
{
    const unsigned FULL = 0xffffffffu;
    int b = blockIdx.z;
    int t = blockIdx.y;
    int tl = __ldg(&logit_lens[b]);
    if (t >= tl) return;
    int yl = __ldg(&y_lens[b]);

    int warp = threadIdx.x >> 5;
    int lane = threadIdx.x & 31;
    int u_base = (blockIdx.x * 8 + warp) * RR;
    if (u_base > yl) return;               // yl <= 100 so this also bounds U1

    int rowbase = (b * TT + t) * U1;

    // Phase A: branch-free loads (clamped index -> always-valid address)
    float v[RR][5];
    #pragma unroll
    for (int r = 0; r < RR; r++) {
        int uc = u_base + r; uc = uc > yl ? yl : uc;
        const float* rp = logits + (size_t)(rowbase + uc) * V1;
        v[r][0] = rp[lane];
        v[r][1] = rp[lane + 32];
        v[r][2] = rp[lane + 64];
        v[r][3] = rp[lane + 96];
        v[r][4] = rp[128];                 // same value all lanes (bcast)
    }

    // Phase B: ex2, per-lane partial sum, early label select
    float s[RR], lv[RR], b0[RR];
    #pragma unroll
    for (int r = 0; r < RR; r++) {
        float e0 = ex2f_raw(v[r][0] * LOG2E);
        float e1 = ex2f_raw(v[r][1] * LOG2E);
        float e2 = ex2f_raw(v[r][2] * LOG2E);
        float e3 = ex2f_raw(v[r][3] * LOG2E);
        float e4 = (lane == 0) ? ex2f_raw(v[r][4] * LOG2E) : 0.0f;
        s[r]  = ((e0 + e1) + (e2 + e3)) + e4;
        b0[r] = e0;
        int u  = u_base + r; u = u > yl ? yl : u;
        int uc = u < UU ? u : UU - 1;
        int lab  = __ldg(&labels[b * UU + uc]);     // warp-uniform
        int slot = lab >> 5;
        int src  = lab & 31;
        float vsel = (slot == 0) ? e0 :
                     (slot == 1) ? e1 :
                     (slot == 2) ? e2 :
                     (slot == 3) ? e3 : e4;
        lv[r] = __shfl_sync(FULL, vsel, src);
    }

    // 8 interleaved butterflies
    #pragma unroll
    for (int o = 16; o > 0; o >>= 1) {
        #pragma unroll
        for (int r = 0; r < RR; r++)
            s[r] += __shfl_xor_sync(FULL, s[r], o);
    }

    int outbase = (b * TT + t) * ST;
    #pragma unroll
    for (int r = 0; r < RR; r++) {
        int u = u_base + r;
        if (u > yl || u >= U1) continue;   // warp-uniform
        float rinv = rcpf_raw(s[r]);
        if (lane == 0) {
            if (u < UU) g_label[outbase + u + 1] = lv[r] * rinv;
            g_blank[outbase + u] = b0[r] * rinv;
        }
    }
}

// ---------------------------------------------------------------------------
// Kernel 2: linear-domain wavefront DP, 8-row x 4-col parallelogram blocks.
// cp.async preload; raw-b3 shuffles with pre-rescale frames (no b3 scaling).
// ---------------------------------------------------------------------------
__global__ void __launch_bounds__(128) dp_kernel(
    const int* __restrict__ logit_lens,
    const int* __restrict__ y_lens,
    float* __restrict__ out)
{
    extern __shared__ float sm[];
    float* sB = sm + 1024;                // 1024-float zeroed front guard
    float* sL = sB + TT * ST;

    int b   = blockIdx.x;
    int tid = threadIdx.x;
    int tl  = logit_lens[b];

    for (int i = tid; i < 1024; i += 128) sm[i] = 0.0f;
    __syncthreads();
    if (tid < 8) sB[-ST * (tid + 1)] = 1.0f;   // seed col0 in guard rows -1..-8
    {   // cp.async full-table preload (tail zeros are guards)
        const float4* srcB = (const float4*)(g_blank + b * TT * ST);
        const float4* srcL = (const float4*)(g_label + b * TT * ST);
        unsigned int dB = (unsigned int)__cvta_generic_to_shared(sB);
        unsigned int dL = (unsigned int)__cvta_generic_to_shared(sL);
        for (int i = tid; i < (TT * ST) / 4; i += 128) {
            cp_async16(dB + i * 16, srcB + i);
            cp_async16(dL + i * 16, srcL + i);
        }
        asm volatile("cp.async.commit_group;");
        asm volatile("cp.async.wait_group 0;");
    }
    __syncthreads();
    if (tid >= 32) return;

    const unsigned FULL = 0xffffffffu;
    int lane  = tid;
    int u0    = lane * 4;
    int yl    = y_lens[b];
    int tlast = tl - 1;
    int pad   = 7 - (tlast & 7);          // tlast lands on block row 7
    int t8max = (tlast >> 3) * 8;
    int laneyl = yl >> 2, cyl = yl & 3;
    int sfin  = laneyl + (tlast >> 3);
    int S     = sfin + 1;
    float fzero = (lane == 0) ? 0.0f : 1.0f;

    float c0 = (lane == 0) ? 1.0f : 0.0f;
    float c1 = 0.f, c2 = 0.f, c3 = 0.f;
    float b3[8], bnd[8];
    #pragma unroll
    for (int k = 0; k < 8; k++) { b3[k] = 0.f; bnd[k] = 0.f; }
    int   Mi = 0, Ml = 0;
    bool  dead = (lane != 0);
    float finL = 1.f; int finM = 0;

    // initial coefficient load (s=0): t0 clamped to 0 for all lanes
    float4 Bc[8], Lc[8];
    {
        int ib = (-pad - 1) * ST + u0;
        int il = (-pad) * ST + u0;
        #pragma unroll
        for (int k = 0; k < 8; k++) {
            Bc[k] = *(const float4*)(sB + ib + k * ST);
            Lc[k] = *(const float4*)(sL + il + k * ST);
        }
    }

    for (int s = 0; s < S; s++) {
        // --- scale reconcile (bnd raw, frame Ml = left's pre-rescale frame) ---
        int  Mn   = dead ? Ml : Mi;
        int  dM   = Ml - Mn;
        dM = dM < -126 ? -126 : (dM > 126 ? 126 : dM);
        float f = __int_as_float((127 + dM) << 23) * fzero;
        Mi = Mn;
        #pragma unroll
        for (int k = 0; k < 8; k++) bnd[k] *= f;

        // --- 8x4 FMA chain ---
        float v0 = c0, v1 = c1, v2 = c2, v3 = c3;
        #pragma unroll
        for (int r = 0; r < 8; r++) {
            float w0 = fmaf(v0, Bc[r].x, bnd[r] * Lc[r].x);
            float w1 = fmaf(v1, Bc[r].y, w0 * Lc[r].y);
            float w2 = fmaf(v2, Bc[r].z, w1 * Lc[r].z);
            float w3 = fmaf(v3, Bc[r].w, w2 * Lc[r].w);
            v0 = w0; v1 = w1; v2 = w2; v3 = w3;
            b3[r] = w3;
        }

        // --- capture final cell (frame Mi, pre-rescale) ---
        bool hit = (s == sfin) & (lane == laneyl);
        float selc = (cyl == 0) ? v0 : (cyl == 1) ? v1 : (cyl == 2) ? v2 : v3;
        finL = hit ? selc : finL;
        finM = hit ? Mi   : finM;

        // --- branch-free power-of-2 rescale (carries only; b3 stays raw) ---
        float cmax = fmaxf(fmaxf(v0, v1), fmaxf(v2, v3));
        int ebits = __float_as_int(cmax) >> 23;
        dead = (ebits == 0);
        int  se = dead ? 127 : (254 - ebits);
        float sc = __int_as_float(se << 23);
        int Mpre = Mi;                        // frame of raw b3 values
        Mi += dead ? 0 : (ebits - 127);
        c0 = v0 * sc; c1 = v1 * sc; c2 = v2 * sc; c3 = v3 * sc;

        // --- tail shfls: raw b3 + pre-rescale frame ---
        Ml = __shfl_up_sync(FULL, Mpre, 1);
        #pragma unroll
        for (int k = 0; k < 8; k++)
            bnd[k] = __shfl_up_sync(FULL, b3[k], 1);

        // --- tail loads for step s+1, directly into live registers ---
        {
            int t0n = 8 * (s + 1 - lane);
            t0n = t0n < 0 ? 0 : (t0n > t8max ? t8max : t0n);
            int ibn = (t0n - pad - 1) * ST + u0;
            int iln = (t0n - pad) * ST + u0;
            #pragma unroll
            for (int k = 0; k < 8; k++) {
                Bc[k] = *(const float4*)(sB + ibn + k * ST);
                Lc[k] = *(const float4*)(sL + iln + k * ST);
            }
        }
    }

    float fL = __shfl_sync(FULL, finL, laneyl);
    int   fM = __shfl_sync(FULL, finM, laneyl);
    if (lane == 0) {
        float total2 = lg2f_raw(fL) + (float)fM + lg2f_raw(sB[tlast * ST + yl]);
        float loss = -total2 * LN2 / (float)yl;
        g_loss[b] = loss;
        __threadfence();
        unsigned ticket = atomicAdd(&g_cnt, 1);
        if (ticket == BB - 1) {
            __threadfence();
            float ssum = 0.0f;
            #pragma unroll
            for (int i = 0; i < BB; i++) ssum += g_loss[i];
            out[0] = ssum / (float)BB;
            g_cnt = 0;
        }
    }
}

extern "C" void kernel_launch(void* const* d_in, const int* in_sizes, int n_in,
                              void* d_out, int out_size)
{
    const float* logits     = (const float*)d_in[0];
    const int*   labels     = (const int*)d_in[1];
    const int*   logit_lens = (const int*)d_in[2];
    const int*   y_lens     = (const int*)d_in[3];
    float* out = (float*)d_out;

    dim3 grid(2, TT, BB);                 // 2 blocks x 8 warps x 8 rows >= 101
    lsm_kernel<<<grid, 256>>>(logits, labels, logit_lens, y_lens);

    size_t smem = (size_t)(1024 + 2 * TT * ST) * sizeof(float);
    cudaFuncSetAttribute(dp_kernel, cudaFuncAttributeMaxDynamicSharedMemorySize, (int)smem);
    dp_kernel<<<BB, 128, smem>>>(logit_lens, y_lens, out);
}

// round 12
// speedup vs baseline: 1.2768x; 1.0502x over previous
#include <cuda_runtime.h>
#include <cstdint>
#include <math.h>

#define BB 16
#define TT 200
#define UU 100
#define U1 101
#define V1 129
#define ST 104                    // padded row stride (mult of 8 -> float4 aligned)
#define RR 8                      // rows per warp in lsm
#define LOG2E 1.4426950408889634f
#define LN2   0.6931471805599453f
#define NINF  (-INFINITY)

// Scratch: LINEAR softmax probs, padded stride. Label table shifted +1 col.
// Zero-init device globals: unwritten rows/cols are load-bearing guards.
__device__ __align__(16) float g_blank[BB * TT * ST];
__device__ __align__(16) float g_label[BB * TT * ST];
__device__ float    g_loss[BB];
__device__ unsigned g_cnt;

__device__ __forceinline__ float ex2f_raw(float x) {
    float y; asm("ex2.approx.f32 %0, %1;" : "=f"(y) : "f"(x)); return y;
}
__device__ __forceinline__ float lg2f_raw(float x) {
    float y; asm("lg2.approx.f32 %0, %1;" : "=f"(y) : "f"(x)); return y;
}
__device__ __forceinline__ float rcpf_raw(float x) {
    float y; asm("rcp.approx.f32 %0, %1;" : "=f"(y) : "f"(x)); return y;
}
__device__ __forceinline__ void cp_async16(unsigned int saddr, const void* gaddr) {
    asm volatile("cp.async.cg.shared.global [%0], [%1], 16;"
                 :: "r"(saddr), "l"(gaddr));
}

// ---------------------------------------------------------------------------
// Kernel 1: softmax. grid=(2,T,B). Warp handles 8 u-rows. Element-128 tail
// handled by ONE lane-parallel load (lane r owns row r's tail) + ONE ex2.
// Stores LINEAR probs: blank[t][u], label shifted to [t][u+1].
// ---------------------------------------------------------------------------
__global__ void __launch_bounds__(256) lsm_kernel(
    const float* __restrict__ logits,
    const int*   __restrict__ labels,
    const int*   __restrict__ logit_lens,
    const int*   __restrict__ y_lens)
{
    const unsigned FULL = 0xffffffffu;
    int b = blockIdx.z;
    int t = blockIdx.y;
    int tl = __ldg(&logit_lens[b]);
    if (t >= tl) return;
    int yl = __ldg(&y_lens[b]);

    int warp = threadIdx.x >> 5;
    int lane = threadIdx.x & 31;
    int u_base = (blockIdx.x * 8 + warp) * RR;
    if (u_base > yl) return;               // yl <= 100 bounds U1 too

    int rowbase = (b * TT + t) * U1;

    // Phase A: branch-free loads (clamped row index -> always-valid address)
    float v[RR][4];
    #pragma unroll
    for (int r = 0; r < RR; r++) {
        int uc = u_base + r; uc = uc > yl ? yl : uc;
        const float* rp = logits + (size_t)(rowbase + uc) * V1;
        v[r][0] = rp[lane];
        v[r][1] = rp[lane + 32];
        v[r][2] = rp[lane + 64];
        v[r][3] = rp[lane + 96];
    }
    // tail: lane L holds element 128 of row (L & 7) (lanes 8..31 duplicate)
    float e4v;
    {
        int uct = u_base + (lane & 7); uct = uct > yl ? yl : uct;
        float t128 = __ldg(logits + (size_t)(rowbase + uct) * V1 + 128);
        e4v = ex2f_raw(t128 * LOG2E);
    }

    // Phase B: ex2, per-lane partial sum, early label select
    float s[RR], lv[RR], b0[RR];
    #pragma unroll
    for (int r = 0; r < RR; r++) {
        float e0 = ex2f_raw(v[r][0] * LOG2E);
        float e1 = ex2f_raw(v[r][1] * LOG2E);
        float e2 = ex2f_raw(v[r][2] * LOG2E);
        float e3 = ex2f_raw(v[r][3] * LOG2E);
        s[r]  = ((e0 + e1) + (e2 + e3)) + ((lane == r) ? e4v : 0.0f);
        b0[r] = e0;
        int u  = u_base + r; u = u > yl ? yl : u;
        int uc = u < UU ? u : UU - 1;
        int lab  = __ldg(&labels[b * UU + uc]);     // warp-uniform, in [1,129)
        int slot = lab >> 5;
        int src  = (slot == 4) ? r : (lab & 31);
        float vsel = (slot == 0) ? e0 :
                     (slot == 1) ? e1 :
                     (slot == 2) ? e2 :
                     (slot == 3) ? e3 : e4v;
        lv[r] = __shfl_sync(FULL, vsel, src);
    }

    // 8 interleaved butterflies
    #pragma unroll
    for (int o = 16; o > 0; o >>= 1) {
        #pragma unroll
        for (int r = 0; r < RR; r++)
            s[r] += __shfl_xor_sync(FULL, s[r], o);
    }

    int outbase = (b * TT + t) * ST;
    #pragma unroll
    for (int r = 0; r < RR; r++) {
        int u = u_base + r;
        if (u > yl || u >= U1) continue;   // warp-uniform
        float rinv = rcpf_raw(s[r]);
        if (lane == 0) {
            if (u < UU) g_label[outbase + u + 1] = lv[r] * rinv;
            g_blank[outbase + u] = b0[r] * rinv;
        }
    }
}

// ---------------------------------------------------------------------------
// Kernel 2: linear-domain wavefront DP, 8x4 parallelogram blocks.
// Frame shfl hoisted to step start; boundary shfls issued MID-CHAIN so their
// latency retires under the remaining FMA chain. cp.async preload.
// ---------------------------------------------------------------------------
__global__ void __launch_bounds__(128) dp_kernel(
    const int* __restrict__ logit_lens,
    const int* __restrict__ y_lens,
    float* __restrict__ out)
{
    extern __shared__ float sm[];
    float* sB = sm + 1024;                // 1024-float zeroed front guard
    float* sL = sB + TT * ST;

    int b   = blockIdx.x;
    int tid = threadIdx.x;
    int tl  = logit_lens[b];

    for (int i = tid; i < 1024; i += 128) sm[i] = 0.0f;
    __syncthreads();
    if (tid < 8) sB[-ST * (tid + 1)] = 1.0f;   // seed col0 in guard rows -1..-8
    {   // cp.async full-table preload (tail zeros are guards)
        const float4* srcB = (const float4*)(g_blank + b * TT * ST);
        const float4* srcL = (const float4*)(g_label + b * TT * ST);
        unsigned int dB = (unsigned int)__cvta_generic_to_shared(sB);
        unsigned int dL = (unsigned int)__cvta_generic_to_shared(sL);
        for (int i = tid; i < (TT * ST) / 4; i += 128) {
            cp_async16(dB + i * 16, srcB + i);
            cp_async16(dL + i * 16, srcL + i);
        }
        asm volatile("cp.async.commit_group;");
        asm volatile("cp.async.wait_group 0;");
    }
    __syncthreads();
    if (tid >= 32) return;

    const unsigned FULL = 0xffffffffu;
    int lane  = tid;
    int u0    = lane * 4;
    int yl    = y_lens[b];
    int tlast = tl - 1;
    int pad   = 7 - (tlast & 7);          // tlast lands on block row 7
    int t8max = (tlast >> 3) * 8;
    int laneyl = yl >> 2, cyl = yl & 3;
    int sfin  = laneyl + (tlast >> 3);
    int S     = sfin + 1;
    float fzero = (lane == 0) ? 0.0f : 1.0f;

    float c0 = (lane == 0) ? 1.0f : 0.0f;
    float c1 = 0.f, c2 = 0.f, c3 = 0.f;
    float bnd[8];
    #pragma unroll
    for (int k = 0; k < 8; k++) bnd[k] = 0.f;
    int   Mi = 0, Ml = 0;
    bool  dead = (lane != 0);
    float finL = 1.f; int finM = 0;

    // initial coefficient load (s=0): t0 clamped to 0 for all lanes
    float4 Bc[8], Lc[8];
    {
        int ib = (-pad - 1) * ST + u0;
        int il = (-pad) * ST + u0;
        #pragma unroll
        for (int k = 0; k < 8; k++) {
            Bc[k] = *(const float4*)(sB + ib + k * ST);
            Lc[k] = *(const float4*)(sL + il + k * ST);
        }
    }

    for (int s = 0; s < S; s++) {
        // --- reconcile; frame shfl for NEXT step issued immediately ---
        int  Mn = dead ? Ml : Mi;
        int  dM = Ml - Mn;
        dM = dM < -126 ? -126 : (dM > 126 ? 126 : dM);
        float f = __int_as_float((127 + dM) << 23) * fzero;
        Mi = Mn;
        int Mln = __shfl_up_sync(FULL, Mn, 1);   // off the critical path
        #pragma unroll
        for (int k = 0; k < 8; k++) bnd[k] *= f;

        // --- 8x4 FMA chain; boundary shfl issued right after each row ---
        float v0 = c0, v1 = c1, v2 = c2, v3 = c3;
        #pragma unroll
        for (int r = 0; r < 8; r++) {
            float w0 = fmaf(v0, Bc[r].x, bnd[r] * Lc[r].x);
            float w1 = fmaf(v1, Bc[r].y, w0 * Lc[r].y);
            float w2 = fmaf(v2, Bc[r].z, w1 * Lc[r].z);
            float w3 = fmaf(v3, Bc[r].w, w2 * Lc[r].w);
            v0 = w0; v1 = w1; v2 = w2; v3 = w3;
            // bnd[r] already consumed (row r, col 0); reuse for next step.
            // raw value, frame Mn — matches Mln sent above.
            bnd[r] = __shfl_up_sync(FULL, w3, 1);
        }

        // --- capture final cell (frame Mi = Mn, pre-rescale) ---
        bool hit = (s == sfin) & (lane == laneyl);
        float selc = (cyl == 0) ? v0 : (cyl == 1) ? v1 : (cyl == 2) ? v2 : v3;
        finL = hit ? selc : finL;
        finM = hit ? Mi   : finM;

        // --- branch-free power-of-2 rescale (carries only) ---
        float cmax = fmaxf(fmaxf(v0, v1), fmaxf(v2, v3));
        int ebits = __float_as_int(cmax) >> 23;
        dead = (ebits == 0);
        int  se = dead ? 127 : (254 - ebits);
        float sc = __int_as_float(se << 23);
        Mi += dead ? 0 : (ebits - 127);
        c0 = v0 * sc; c1 = v1 * sc; c2 = v2 * sc; c3 = v3 * sc;
        Ml = Mln;

        // --- tail loads for step s+1, directly into live registers ---
        {
            int t0n = 8 * (s + 1 - lane);
            t0n = t0n < 0 ? 0 : (t0n > t8max ? t8max : t0n);
            int ibn = (t0n - pad - 1) * ST + u0;
            int iln = (t0n - pad) * ST + u0;
            #pragma unroll
            for (int k = 0; k < 8; k++) {
                Bc[k] = *(const float4*)(sB + ibn + k * ST);
                Lc[k] = *(const float4*)(sL + iln + k * ST);
            }
        }
    }

    float fL = __shfl_sync(FULL, finL, laneyl);
    int   fM = __shfl_sync(FULL, finM, laneyl);
    if (lane == 0) {
        float total2 = lg2f_raw(fL) + (float)fM + lg2f_raw(sB[tlast * ST + yl]);
        float loss = -total2 * LN2 / (float)yl;
        g_loss[b] = loss;
        __threadfence();
        unsigned ticket = atomicAdd(&g_cnt, 1);
        if (ticket == BB - 1) {
            __threadfence();
            float ssum = 0.0f;
            #pragma unroll
            for (int i = 0; i < BB; i++) ssum += g_loss[i];
            out[0] = ssum / (float)BB;
            g_cnt = 0;
        }
    }
}

extern "C" void kernel_launch(void* const* d_in, const int* in_sizes, int n_in,
                              void* d_out, int out_size)
{
    const float* logits     = (const float*)d_in[0];
    const int*   labels     = (const int*)d_in[1];
    const int*   logit_lens = (const int*)d_in[2];
    const int*   y_lens     = (const int*)d_in[3];
    float* out = (float*)d_out;

    dim3 grid(2, TT, BB);                 // 2 blocks x 8 warps x 8 rows >= 101
    lsm_kernel<<<grid, 256>>>(logits, labels, logit_lens, y_lens);

    size_t smem = (size_t)(1024 + 2 * TT * ST) * sizeof(float);
    cudaFuncSetAttribute(dp_kernel, cudaFuncAttributeMaxDynamicSharedMemorySize, (int)smem);
    dp_kernel<<<BB, 128, smem>>>(logit_lens, y_lens, out);
}